// round 3
// baseline (speedup 1.0000x reference)
#include <cuda_runtime.h>
#include <stdint.h>

#define NBINS    4096
#define CAND_CAP 2048
#define MAXN     524288
#define KSEL     64
#define GRID     592
#define TPB      256

// Scratch (no allocations; __device__ globals). Zero at module load; the
// kernel leaves g_hist/g_count zeroed for the next graph replay. g_gen/g_arrive
// follow sense-reversing semantics and need no reset.
__device__ uint32_t            g_keys[MAXN];
__device__ uint32_t            g_hist[NBINS];
__device__ int                 g_count;
__device__ volatile int        g_countSnap;
__device__ unsigned long long  g_cand[CAND_CAP];
__device__ int                 g_arrive;
__device__ volatile int        g_gen;

__device__ __forceinline__ uint32_t f2key(float f) {
    uint32_t u = __float_as_uint(f);
    return (u & 0x80000000u) ? ~u : (u | 0x80000000u);
}
__device__ __forceinline__ float dot4(float4 a, float4 b) {
    return a.x*b.x + a.y*b.y + a.z*b.z + a.w*b.w;
}

// Sense-reversing grid barrier. Safe: all GRID blocks are co-resident
// (enforced by __launch_bounds__(TPB, 4) -> 4 CTAs/SM x 148 SMs = 592).
__device__ __forceinline__ void grid_barrier(bool snapCount) {
    __syncthreads();
    if (threadIdx.x == 0) {
        __threadfence();
        int gen = g_gen;
        if (atomicAdd(&g_arrive, 1) == GRID - 1) {
            if (snapCount) {            // all compact writes complete here
                g_countSnap = g_count;  // publish
                g_count = 0;            // clean for next replay
            }
            g_arrive = 0;
            __threadfence();
            g_gen = gen + 1;
        } else {
            while (g_gen == gen) __nanosleep(32);
        }
    }
    __syncthreads();
}

__global__ void __launch_bounds__(TPB, 4)
k_fused(const float4* __restrict__ q, const float4* __restrict__ mat,
        int N, float* __restrict__ out, int out_size) {
    __shared__ __align__(8) uint32_t sh[NBINS];   // hist, later reused as cand buf
    __shared__ uint32_t coarse[64];
    __shared__ int      sB;
    __shared__ uint32_t rows[KSEL];

    const int tid = threadIdx.x;

    // ---------- Phase 1: scores + local histogram ----------
    for (int i = tid; i < NBINS; i += TPB) sh[i] = 0u;
    __syncthreads();

    const int lane   = tid & 31;
    const int warp   = (blockIdx.x * TPB + tid) >> 5;
    const int nwarps = (GRID * TPB) >> 5;

    const float4 qa = q[lane];
    const float4 qb = q[lane + 32];

    for (int r0 = warp * 4; r0 < N; r0 += nwarps * 4) {
        const float4* p = mat + (size_t)r0 * 64;
        if (r0 + 3 < N) {
            float4 a0 = p[lane],       b0 = p[lane + 32];
            float4 a1 = p[lane + 64],  b1 = p[lane + 96];
            float4 a2 = p[lane + 128], b2 = p[lane + 160];
            float4 a3 = p[lane + 192], b3 = p[lane + 224];
            float s0 = dot4(a0, qa) + dot4(b0, qb);
            float s1 = dot4(a1, qa) + dot4(b1, qb);
            float s2 = dot4(a2, qa) + dot4(b2, qb);
            float s3 = dot4(a3, qa) + dot4(b3, qb);
            #pragma unroll
            for (int o = 16; o; o >>= 1) {
                s0 += __shfl_xor_sync(0xffffffffu, s0, o);
                s1 += __shfl_xor_sync(0xffffffffu, s1, o);
                s2 += __shfl_xor_sync(0xffffffffu, s2, o);
                s3 += __shfl_xor_sync(0xffffffffu, s3, o);
            }
            if (lane < 4) {
                float s = (lane == 0) ? s0 : (lane == 1) ? s1 : (lane == 2) ? s2 : s3;
                uint32_t key = f2key(s);
                g_keys[r0 + lane] = key;
                atomicAdd(&sh[key >> 20], 1u);
            }
        } else {
            for (int r = r0; r < N; r++) {
                const float4* row = mat + (size_t)r * 64;
                float s = dot4(row[lane], qa) + dot4(row[lane + 32], qb);
                #pragma unroll
                for (int o = 16; o; o >>= 1) s += __shfl_xor_sync(0xffffffffu, s, o);
                if (lane == 0) {
                    uint32_t key = f2key(s);
                    g_keys[r] = key;
                    atomicAdd(&sh[key >> 20], 1u);
                }
            }
        }
    }
    __syncthreads();
    for (int i = tid; i < NBINS; i += TPB) {
        uint32_t c = sh[i];
        if (c) atomicAdd(&g_hist[i], c);
    }

    grid_barrier(false);   // ---- barrier 1: histogram complete ----

    // ---------- Phase 2: every block computes threshold bin B ----------
    if (tid < 64) {
        uint32_t s = 0;
        #pragma unroll 4
        for (int j = 0; j < 64; j++) s += g_hist[tid * 64 + j];
        coarse[tid] = s;
    }
    __syncthreads();
    if (tid == 0) {
        long long cum = 0;
        int cb = 63;
        for (; cb >= 0; cb--) { cum += coarse[cb]; if (cum >= KSEL) break; }
        if (cb < 0) cb = 0;
        long long c2 = cum - coarse[cb];
        int B = cb * 64;
        for (int b = cb * 64 + 63; b >= cb * 64; b--) {
            c2 += g_hist[b];
            if (c2 >= KSEL) { B = b; break; }
        }
        sB = B;
    }
    __syncthreads();
    const int B = sB;

    // ---------- Phase 3: compact candidates (one uint4 per thread) ----------
    {
        const uint4* keys4 = (const uint4*)g_keys;
        const int N4 = N >> 2;
        for (int i = blockIdx.x * TPB + tid; i < N4; i += GRID * TPB) {
            uint4 k4 = keys4[i];
            uint32_t base = (uint32_t)i * 4u;
            #pragma unroll
            for (int j = 0; j < 4; j++) {
                uint32_t key = (j == 0) ? k4.x : (j == 1) ? k4.y : (j == 2) ? k4.z : k4.w;
                if ((int)(key >> 20) >= B) {
                    int p = atomicAdd(&g_count, 1);
                    if (p < CAND_CAP)
                        g_cand[p] = ((unsigned long long)key << 32)
                                  | (uint32_t)(~(base + (uint32_t)j));
                }
            }
        }
    }

    grid_barrier(true);    // ---- barrier 2: candidates complete, count snapped & reset ----

    // ---------- Phase 4: parallel select + gather ----------
    if (blockIdx.x < KSEL) {
        // Redundant rank computation per block (C ~ 100, trivial).
        int C = g_countSnap;
        if (C > CAND_CAP) C = CAND_CAP;
        unsigned long long* cv = (unsigned long long*)sh;   // hist is dead; reuse
        for (int j = tid; j < C; j += TPB) cv[j] = g_cand[j];
        __syncthreads();
        for (int j = tid; j < C; j += TPB) {
            unsigned long long v = cv[j];
            int rank = 0;
            for (int i = 0; i < C; i++) rank += (cv[i] > v);
            if (rank < KSEL) rows[rank] = ~(uint32_t)(v & 0xFFFFFFFFull);
        }
        __syncthreads();

        // This block gathers exactly one output row (64 float4 = 1 KB).
        const int r = blockIdx.x;
        float4* out4 = (float4*)out;
        if (tid < 64)
            out4[r * 64 + tid] = mat[(size_t)rows[r] * 64 + tid];
        // Block 0 also emits the index vector (as float).
        if (r == 0 && tid < KSEL && out_size >= KSEL * 256 + KSEL)
            out[KSEL * 256 + tid] = (float)rows[tid];
    } else if (blockIdx.x < KSEL + 16) {
        // Zero the global histogram for the next graph replay (hist is dead
        // for everyone after barrier 2).
        int idx = (blockIdx.x - KSEL) * TPB + tid;
        g_hist[idx] = 0u;
    }
}

extern "C" void kernel_launch(void* const* d_in, const int* in_sizes, int n_in,
                              void* d_out, int out_size) {
    const float* q   = (const float*)d_in[0];   // [256]
    const float* mat = (const float*)d_in[1];   // [500000, 256]
    int D = in_sizes[0];
    int N = in_sizes[1] / D;

    k_fused<<<GRID, TPB>>>((const float4*)q, (const float4*)mat, N,
                           (float*)d_out, out_size);
}

// round 4
// speedup vs baseline: 1.0682x; 1.0682x over previous
#include <cuda_runtime.h>
#include <stdint.h>

#define NBINS    4096
#define CAND_CAP 2048
#define MAXN     524288
#define KSEL     64
#define TPB      256
#define SGRID    592

// Scratch (no allocations; __device__ globals). Zero-initialized at module
// load. Reset protocol per replay: k_score block0 zeros g_count at start
// (g_count is only touched later, in k_compact — stream order guarantees
// safety); k_select blocks 64-79 zero g_hist (dead after k_compact).
__device__ uint32_t            g_keys[MAXN];
__device__ uint32_t            g_hist[NBINS];
__device__ int                 g_count;
__device__ unsigned long long  g_cand[CAND_CAP];

__device__ __forceinline__ uint32_t f2key(float f) {
    uint32_t u = __float_as_uint(f);
    return (u & 0x80000000u) ? ~u : (u | 0x80000000u);
}
__device__ __forceinline__ float dot4(float4 a, float4 b) {
    return a.x*b.x + a.y*b.y + a.z*b.z + a.w*b.w;
}

// K1: 4 rows per warp iteration -> 8 independent LDG.128 in flight per warp.
// Fused shared-mem histogram on top 12 key bits. No launch bounds: let the
// compiler pick registers freely (this was the R2 regression).
__global__ void k_score(const float4* __restrict__ q,
                        const float4* __restrict__ mat, int N) {
    __shared__ uint32_t sh[NBINS];
    if (blockIdx.x == 0 && threadIdx.x == 0) g_count = 0;   // replay reset
    for (int i = threadIdx.x; i < NBINS; i += TPB) sh[i] = 0u;
    __syncthreads();

    const int lane   = threadIdx.x & 31;
    const int warp   = (blockIdx.x * TPB + threadIdx.x) >> 5;
    const int nwarps = (gridDim.x * TPB) >> 5;

    const float4 qa = q[lane];
    const float4 qb = q[lane + 32];

    for (int r0 = warp * 4; r0 < N; r0 += nwarps * 4) {
        const float4* p = mat + (size_t)r0 * 64;
        if (r0 + 3 < N) {
            float4 a0 = p[lane],       b0 = p[lane + 32];
            float4 a1 = p[lane + 64],  b1 = p[lane + 96];
            float4 a2 = p[lane + 128], b2 = p[lane + 160];
            float4 a3 = p[lane + 192], b3 = p[lane + 224];
            float s0 = dot4(a0, qa) + dot4(b0, qb);
            float s1 = dot4(a1, qa) + dot4(b1, qb);
            float s2 = dot4(a2, qa) + dot4(b2, qb);
            float s3 = dot4(a3, qa) + dot4(b3, qb);
            #pragma unroll
            for (int o = 16; o; o >>= 1) {
                s0 += __shfl_xor_sync(0xffffffffu, s0, o);
                s1 += __shfl_xor_sync(0xffffffffu, s1, o);
                s2 += __shfl_xor_sync(0xffffffffu, s2, o);
                s3 += __shfl_xor_sync(0xffffffffu, s3, o);
            }
            if (lane < 4) {
                float s = (lane == 0) ? s0 : (lane == 1) ? s1 : (lane == 2) ? s2 : s3;
                uint32_t key = f2key(s);
                g_keys[r0 + lane] = key;
                atomicAdd(&sh[key >> 20], 1u);
            }
        } else {
            for (int r = r0; r < N; r++) {
                const float4* row = mat + (size_t)r * 64;
                float s = dot4(row[lane], qa) + dot4(row[lane + 32], qb);
                #pragma unroll
                for (int o = 16; o; o >>= 1) s += __shfl_xor_sync(0xffffffffu, s, o);
                if (lane == 0) {
                    uint32_t key = f2key(s);
                    g_keys[r] = key;
                    atomicAdd(&sh[key >> 20], 1u);
                }
            }
        }
    }
    __syncthreads();
    for (int i = threadIdx.x; i < NBINS; i += TPB) {
        uint32_t c = sh[i];
        if (c) atomicAdd(&g_hist[i], c);
    }
}

// K2: each block redundantly computes threshold bin B from the (L2-hot)
// global histogram, then compacts its slice of keys.
__global__ void k_compact(int N4) {
    __shared__ uint32_t coarse[64];
    __shared__ int sB;
    const int tid = threadIdx.x;

    if (tid < 64) {
        uint32_t s = 0;
        #pragma unroll 4
        for (int j = 0; j < 64; j++) s += g_hist[tid * 64 + j];
        coarse[tid] = s;
    }
    __syncthreads();
    if (tid == 0) {
        long long cum = 0;
        int cb = 63;
        for (; cb >= 0; cb--) { cum += coarse[cb]; if (cum >= KSEL) break; }
        if (cb < 0) cb = 0;
        long long c2 = cum - coarse[cb];
        int B = cb * 64;
        for (int b = cb * 64 + 63; b >= cb * 64; b--) {
            c2 += g_hist[b];
            if (c2 >= KSEL) { B = b; break; }
        }
        sB = B;
    }
    __syncthreads();
    const int B = sB;

    const uint4* keys4 = (const uint4*)g_keys;
    const int stride = gridDim.x * TPB;
    for (int i = blockIdx.x * TPB + tid; i < N4; i += stride) {
        uint4 k4 = keys4[i];
        uint32_t base = (uint32_t)i * 4u;
        #pragma unroll
        for (int j = 0; j < 4; j++) {
            uint32_t key = (j == 0) ? k4.x : (j == 1) ? k4.y : (j == 2) ? k4.z : k4.w;
            if ((int)(key >> 20) >= B) {
                int p = atomicAdd(&g_count, 1);
                if (p < CAND_CAP)
                    g_cand[p] = ((unsigned long long)key << 32)
                              | (uint32_t)(~(base + (uint32_t)j));
            }
        }
    }
}

// K3: blocks 0-63: redundant rank computation (packed keys unique -> unique
// ranks; rank<64 selects) + gather ONE output row each. Block 0 also writes
// the index vector. Blocks 64-79: zero g_hist for the next replay.
__global__ void k_select(const float4* __restrict__ mat,
                         float* __restrict__ out, int out_size) {
    if (blockIdx.x >= KSEL) {
        int idx = (blockIdx.x - KSEL) * TPB + threadIdx.x;
        g_hist[idx] = 0u;
        return;
    }

    __shared__ unsigned long long cv[CAND_CAP];
    __shared__ uint32_t rows[KSEL];
    const int tid = threadIdx.x;

    int C = g_count;
    if (C > CAND_CAP) C = CAND_CAP;

    for (int j = tid; j < C; j += TPB) cv[j] = g_cand[j];
    __syncthreads();
    for (int j = tid; j < C; j += TPB) {
        unsigned long long v = cv[j];
        int rank = 0;
        for (int i = 0; i < C; i++) rank += (cv[i] > v);
        if (rank < KSEL) rows[rank] = ~(uint32_t)(v & 0xFFFFFFFFull);
    }
    __syncthreads();

    const int r = blockIdx.x;
    float4* out4 = (float4*)out;
    if (tid < 64)
        out4[r * 64 + tid] = mat[(size_t)rows[r] * 64 + tid];
    if (r == 0 && tid < KSEL && out_size >= KSEL * 256 + KSEL)
        out[KSEL * 256 + tid] = (float)rows[tid];
}

extern "C" void kernel_launch(void* const* d_in, const int* in_sizes, int n_in,
                              void* d_out, int out_size) {
    const float* q   = (const float*)d_in[0];   // [256]
    const float* mat = (const float*)d_in[1];   // [500000, 256]
    int D = in_sizes[0];
    int N = in_sizes[1] / D;

    k_score<<<SGRID, TPB>>>((const float4*)q, (const float4*)mat, N);
    k_compact<<<SGRID, TPB>>>(N / 4);
    k_select<<<KSEL + NBINS / TPB, TPB>>>((const float4*)mat, (float*)d_out, out_size);
}